// round 14
// baseline (speedup 1.0000x reference)
#include <cuda_runtime.h>
#include <cuda_fp16.h>
#include <cstdint>

// fp16 copies of the embedding tables (row = 128 halves = 256B = 16 uint4).
#define N_ROWS_MAX 100000
__device__ uint4 g_user_h[N_ROWS_MAX * 16];
__device__ uint4 g_item_h[N_ROWS_MAX * 16];

static __device__ __forceinline__ unsigned h2bits(__half2 h)
{
    return *reinterpret_cast<unsigned*>(&h);
}

// Wide streaming fp32 -> fp16: each thread reads 2 x float4 (32B), writes
// 1 x uint4 (16B). ~7 TB/s effective; at the DRAM floor for this pass.
__global__ __launch_bounds__(256) void convert_f32_to_f16_kernel(
    const float4* __restrict__ src, uint4* __restrict__ dst, int n8)
{
    int i = blockIdx.x * blockDim.x + threadIdx.x;
    if (i >= n8) return;
    float4 v0 = __ldcs(&src[2 * i]);
    float4 v1 = __ldcs(&src[2 * i + 1]);
    uint4 o;
    o.x = h2bits(__floats2half2_rn(v0.x, v0.y));
    o.y = h2bits(__floats2half2_rn(v0.z, v0.w));
    o.z = h2bits(__floats2half2_rn(v1.x, v1.y));
    o.w = h2bits(__floats2half2_rn(v1.z, v1.w));
    __stcs(&dst[i], o);
}

// Accumulate dot of 8 fp16 pairs (16B vs 16B) into two fp32 chains.
__device__ __forceinline__ void acc16(const uint4& a, const uint4& b,
                                      float2& acc)
{
    const unsigned aw[4] = {a.x, a.y, a.z, a.w};
    const unsigned bw[4] = {b.x, b.y, b.z, b.w};
    #pragma unroll
    for (int i = 0; i < 4; i++) {
        __half2 ha = *reinterpret_cast<const __half2*>(&aw[i]);
        __half2 hb = *reinterpret_cast<const __half2*>(&bw[i]);
        float2 fa = __half22float2(ha);
        float2 fb = __half22float2(hb);
        acc.x = fmaf(fa.x, fb.x, acc.x);
        acc.y = fmaf(fa.y, fb.y, acc.y);
    }
}

// Proven scorer inner loop: 4 lanes per edge, 8 edges per warp, fp16 rows
// (256B = 16 x 16B chunks). Lane covers chunks {sub, sub+4, sub+8, sub+12}
// of both rows -> 8 independent LDG.128 per thread (MLP=8), ~32 regs.
__device__ __forceinline__ float dot_rows4(const uint4* __restrict__ srow,
                                           const uint4* __restrict__ drow,
                                           int sub)
{
    uint4 a0 = __ldg(&srow[sub]);
    uint4 b0 = __ldg(&drow[sub]);
    uint4 a1 = __ldg(&srow[sub + 4]);
    uint4 b1 = __ldg(&drow[sub + 4]);
    uint4 a2 = __ldg(&srow[sub + 8]);
    uint4 b2 = __ldg(&drow[sub + 8]);
    uint4 a3 = __ldg(&srow[sub + 12]);
    uint4 b3 = __ldg(&drow[sub + 12]);

    float2 acc0 = make_float2(0.f, 0.f);
    float2 acc1 = make_float2(0.f, 0.f);
    acc16(a0, b0, acc0);
    acc16(a1, b1, acc1);
    acc16(a2, b2, acc0);
    acc16(a3, b3, acc1);
    return (acc0.x + acc0.y) + (acc1.x + acc1.y);
}

// Fused 2-etype scorer (clicks: user->item, clickedby: item->user).
// No iteration batching: lean registers, max occupancy, one big grid.
__global__ __launch_bounds__(256) void edge_dot2_h_kernel(
    const int* __restrict__ si0, const int* __restrict__ di0,
    const int* __restrict__ si1, const int* __restrict__ di1,
    float* __restrict__ out, int E)
{
    const int lane = threadIdx.x & 31;
    const int wib = threadIdx.x >> 5;
    const int sub = lane & 3;
    const int group = lane >> 2;

    // 64 edges per block (8 warps x 8 edges)
    const int e = blockIdx.x * 64 + wib * 8 + group;
    const int total = 2 * E;
    if (e >= total) return;

    const uint4* sT; const uint4* dT;
    const int* si; const int* di; int el;
    if (e < E) { sT = g_user_h; dT = g_item_h; si = si0; di = di0; el = e; }
    else       { sT = g_item_h; dT = g_user_h; si = si1; di = di1; el = e - E; }

    const int s_idx = __ldcs(&si[el]);
    const int d_idx = __ldcs(&di[el]);

    float sum = dot_rows4(sT + (size_t)s_idx * 16,
                          dT + (size_t)d_idx * 16, sub);

    sum += __shfl_xor_sync(0xFFFFFFFFu, sum, 1);
    sum += __shfl_xor_sync(0xFFFFFFFFu, sum, 2);

    if (sub == 0) __stcs(&out[e], sum);
}

// Single-etype scorer for follows (user->user), same 4-lane shape.
__global__ __launch_bounds__(256) void edge_dot1_h_kernel(
    const int* __restrict__ si, const int* __restrict__ di,
    float* __restrict__ out, int E)
{
    const int lane = threadIdx.x & 31;
    const int wib = threadIdx.x >> 5;
    const int sub = lane & 3;
    const int group = lane >> 2;

    const int e = blockIdx.x * 64 + wib * 8 + group;
    if (e >= E) return;

    const int s_idx = __ldcs(&si[e]);
    const int d_idx = __ldcs(&di[e]);

    float sum = dot_rows4(g_user_h + (size_t)s_idx * 16,
                          g_user_h + (size_t)d_idx * 16, sub);

    sum += __shfl_xor_sync(0xFFFFFFFFu, sum, 1);
    sum += __shfl_xor_sync(0xFFFFFFFFu, sum, 2);

    if (sub == 0) __stcs(&out[e], sum);
}

extern "C" void kernel_launch(void* const* d_in, const int* in_sizes, int n_in,
                              void* d_out, int out_size)
{
    const float* h_user = (const float*)d_in[0];
    const float* h_item = (const float*)d_in[1];
    const int* src_clicks    = (const int*)d_in[2];
    const int* dst_clicks    = (const int*)d_in[3];
    const int* src_clickedby = (const int*)d_in[4];
    const int* dst_clickedby = (const int*)d_in[5];
    const int* src_follows   = (const int*)d_in[6];
    const int* dst_follows   = (const int*)d_in[7];
    float* out = (float*)d_out;

    const int E = in_sizes[2];          // edges per etype (500000)

    static cudaStream_t s1 = nullptr;
    static cudaEvent_t ev_user = nullptr, ev_follows = nullptr;
    if (!s1) {
        cudaStreamCreateWithFlags(&s1, cudaStreamNonBlocking);
        cudaEventCreateWithFlags(&ev_user, cudaEventDisableTiming);
        cudaEventCreateWithFlags(&ev_follows, cudaEventDisableTiming);
    }

    uint4* gu = nullptr; uint4* gi = nullptr;
    cudaGetSymbolAddress((void**)&gu, g_user_h);
    cudaGetSymbolAddress((void**)&gi, g_item_h);
    const int n8u = in_sizes[0] / 8;
    const int n8i = in_sizes[1] / 8;

    const int blocks1 = (E + 63) / 64;          // 64 edges per block
    const int blocks2 = (2 * E + 63) / 64;

    // 1) Convert user table (origin stream).
    convert_f32_to_f16_kernel<<<(n8u + 255) / 256, 256>>>(
        (const float4*)h_user, gu, n8u);

    // 2) Fork: follows (user-only, L2-gather-bound) on s1, overlapped with
    //    convert_item (DRAM-stream-bound) on origin.
    cudaEventRecord(ev_user, 0);
    cudaStreamWaitEvent(s1, ev_user, 0);
    edge_dot1_h_kernel<<<blocks1, 256, 0, s1>>>(
        src_follows, dst_follows, out + 2 * (size_t)E, E);
    cudaEventRecord(ev_follows, s1);

    // 3) Convert item table, then fused clicks+clickedby (one big grid).
    convert_f32_to_f16_kernel<<<(n8i + 255) / 256, 256>>>(
        (const float4*)h_item, gi, n8i);
    edge_dot2_h_kernel<<<blocks2, 256>>>(
        src_clicks, dst_clicks, src_clickedby, dst_clickedby, out, E);

    // 4) Join the fork back into the origin stream.
    cudaStreamWaitEvent(0, ev_follows, 0);
}

// round 15
// speedup vs baseline: 1.3942x; 1.3942x over previous
#include <cuda_runtime.h>
#include <cuda_fp16.h>
#include <cstdint>

// fp16 copies of the embedding tables (row = 128 halves = 256B = 16 uint4).
#define N_ROWS_MAX 100000
__device__ uint4 g_user_h[N_ROWS_MAX * 16];
__device__ uint4 g_item_h[N_ROWS_MAX * 16];

static __device__ __forceinline__ unsigned h2bits(__half2 h)
{
    return *reinterpret_cast<unsigned*>(&h);
}

// Wide streaming fp32 -> fp16: each thread reads 2 x float4 (32B), writes
// 1 x uint4 (16B). Near the DRAM floor for this pass (~11us per table).
__global__ __launch_bounds__(256) void convert_f32_to_f16_kernel(
    const float4* __restrict__ src, uint4* __restrict__ dst, int n8)
{
    int i = blockIdx.x * blockDim.x + threadIdx.x;
    if (i >= n8) return;
    float4 v0 = __ldcs(&src[2 * i]);
    float4 v1 = __ldcs(&src[2 * i + 1]);
    uint4 o;
    o.x = h2bits(__floats2half2_rn(v0.x, v0.y));
    o.y = h2bits(__floats2half2_rn(v0.z, v0.w));
    o.z = h2bits(__floats2half2_rn(v1.x, v1.y));
    o.w = h2bits(__floats2half2_rn(v1.z, v1.w));
    __stcs(&dst[i], o);
}

// Accumulate dot of 8 fp16 pairs (16B vs 16B) into two fp32 chains.
__device__ __forceinline__ void acc16(const uint4& a, const uint4& b,
                                      float2& acc)
{
    const unsigned aw[4] = {a.x, a.y, a.z, a.w};
    const unsigned bw[4] = {b.x, b.y, b.z, b.w};
    #pragma unroll
    for (int i = 0; i < 4; i++) {
        __half2 ha = *reinterpret_cast<const __half2*>(&aw[i]);
        __half2 hb = *reinterpret_cast<const __half2*>(&bw[i]);
        float2 fa = __half22float2(ha);
        float2 fb = __half22float2(hb);
        acc.x = fmaf(fa.x, fb.x, acc.x);
        acc.y = fmaf(fa.y, fb.y, acc.y);
    }
}

// Proven scorer inner loop: 4 lanes per edge, 8 edges per warp, fp16 rows
// (256B = 16 x 16B chunks). Lane covers chunks {sub, sub+4, sub+8, sub+12}
// of both rows -> 8 independent LDG.128 per thread (MLP=8), ~32 regs.
__device__ __forceinline__ float dot_rows4(const uint4* __restrict__ srow,
                                           const uint4* __restrict__ drow,
                                           int sub)
{
    uint4 a0 = __ldg(&srow[sub]);
    uint4 b0 = __ldg(&drow[sub]);
    uint4 a1 = __ldg(&srow[sub + 4]);
    uint4 b1 = __ldg(&drow[sub + 4]);
    uint4 a2 = __ldg(&srow[sub + 8]);
    uint4 b2 = __ldg(&drow[sub + 8]);
    uint4 a3 = __ldg(&srow[sub + 12]);
    uint4 b3 = __ldg(&drow[sub + 12]);

    float2 acc0 = make_float2(0.f, 0.f);
    float2 acc1 = make_float2(0.f, 0.f);
    acc16(a0, b0, acc0);
    acc16(a1, b1, acc1);
    acc16(a2, b2, acc0);
    acc16(a3, b3, acc1);
    return (acc0.x + acc0.y) + (acc1.x + acc1.y);
}

// Single-etype scorer (srcTab/dstTab passed explicitly; clean access stream).
__global__ __launch_bounds__(256) void edge_dot1_h_kernel(
    const uint4* __restrict__ srcTab, const int* __restrict__ si,
    const uint4* __restrict__ dstTab, const int* __restrict__ di,
    float* __restrict__ out, int E)
{
    const int lane = threadIdx.x & 31;
    const int wib = threadIdx.x >> 5;
    const int sub = lane & 3;
    const int group = lane >> 2;

    const int e = blockIdx.x * 64 + wib * 8 + group;
    if (e >= E) return;

    const int s_idx = __ldcs(&si[e]);
    const int d_idx = __ldcs(&di[e]);

    float sum = dot_rows4(srcTab + (size_t)s_idx * 16,
                          dstTab + (size_t)d_idx * 16, sub);

    sum += __shfl_xor_sync(0xFFFFFFFFu, sum, 1);
    sum += __shfl_xor_sync(0xFFFFFFFFu, sum, 2);

    if (sub == 0) __stcs(&out[e], sum);
}

extern "C" void kernel_launch(void* const* d_in, const int* in_sizes, int n_in,
                              void* d_out, int out_size)
{
    const float* h_user = (const float*)d_in[0];
    const float* h_item = (const float*)d_in[1];
    const int* src_clicks    = (const int*)d_in[2];
    const int* dst_clicks    = (const int*)d_in[3];
    const int* src_clickedby = (const int*)d_in[4];
    const int* dst_clickedby = (const int*)d_in[5];
    const int* src_follows   = (const int*)d_in[6];
    const int* dst_follows   = (const int*)d_in[7];
    float* out = (float*)d_out;

    const int E = in_sizes[2];          // edges per etype (500000)

    static cudaStream_t s1 = nullptr;
    static cudaEvent_t ev_user = nullptr, ev_item = nullptr, ev_s1 = nullptr;
    if (!s1) {
        cudaStreamCreateWithFlags(&s1, cudaStreamNonBlocking);
        cudaEventCreateWithFlags(&ev_user, cudaEventDisableTiming);
        cudaEventCreateWithFlags(&ev_item, cudaEventDisableTiming);
        cudaEventCreateWithFlags(&ev_s1, cudaEventDisableTiming);
    }

    uint4* gu = nullptr; uint4* gi = nullptr;
    cudaGetSymbolAddress((void**)&gu, g_user_h);
    cudaGetSymbolAddress((void**)&gi, g_item_h);
    const int n8u = in_sizes[0] / 8;
    const int n8i = in_sizes[1] / 8;

    const int sblocks = (E + 63) / 64;  // 64 edges per block

    // origin: conv_user -> ev_user -> conv_item -> ev_item -> clicks -> wait s1
    // s1:     wait ev_user -> follows -> wait ev_item -> clickedby -> ev_s1
    //
    // follows overlaps conv_item (L2-gather vs DRAM-stream, disjoint).
    // clickedby overlaps clicks (two co-resident gather kernels -> aggregate
    // throughput rises toward the big-grid 15.4 TB/s regime).

    convert_f32_to_f16_kernel<<<(n8u + 255) / 256, 256>>>(
        (const float4*)h_user, gu, n8u);
    cudaEventRecord(ev_user, 0);

    cudaStreamWaitEvent(s1, ev_user, 0);
    edge_dot1_h_kernel<<<sblocks, 256, 0, s1>>>(
        gu, src_follows, gu, dst_follows, out + 2 * (size_t)E, E);

    convert_f32_to_f16_kernel<<<(n8i + 255) / 256, 256>>>(
        (const float4*)h_item, gi, n8i);
    cudaEventRecord(ev_item, 0);

    cudaStreamWaitEvent(s1, ev_item, 0);
    edge_dot1_h_kernel<<<sblocks, 256, 0, s1>>>(
        gi, src_clickedby, gu, dst_clickedby, out + (size_t)E, E);
    cudaEventRecord(ev_s1, s1);

    edge_dot1_h_kernel<<<sblocks, 256>>>(
        gu, src_clicks, gi, dst_clicks, out, E);

    cudaStreamWaitEvent(0, ev_s1, 0);
}

// round 16
// speedup vs baseline: 1.4207x; 1.0190x over previous
#include <cuda_runtime.h>
#include <cuda_fp16.h>
#include <cstdint>

// fp16 copies of the embedding tables (row = 128 halves = 256B = 16 uint4).
// Combined 51.2MB -> fits entirely in the 126MB L2. Convert writes use
// DEFAULT (evict-normal) policy so the tables STAY resident for the scorers
// (previous rounds used __stcs = evict-first, forcing every scorer to re-pull
// the whole table from DRAM).
#define N_ROWS_MAX 100000
__device__ uint4 g_user_h[N_ROWS_MAX * 16];
__device__ uint4 g_item_h[N_ROWS_MAX * 16];

static __device__ __forceinline__ unsigned h2bits(__half2 h)
{
    return *reinterpret_cast<unsigned*>(&h);
}

// Wide streaming fp32 -> fp16: each thread reads 2 x float4 (32B, evict-first:
// fp32 source is single-use), writes 1 x uint4 (16B, DEFAULT policy: the fp16
// table must remain L2-resident).
__global__ __launch_bounds__(256) void convert_f32_to_f16_kernel(
    const float4* __restrict__ src, uint4* __restrict__ dst, int n8)
{
    int i = blockIdx.x * blockDim.x + threadIdx.x;
    if (i >= n8) return;
    float4 v0 = __ldcs(&src[2 * i]);
    float4 v1 = __ldcs(&src[2 * i + 1]);
    uint4 o;
    o.x = h2bits(__floats2half2_rn(v0.x, v0.y));
    o.y = h2bits(__floats2half2_rn(v0.z, v0.w));
    o.z = h2bits(__floats2half2_rn(v1.x, v1.y));
    o.w = h2bits(__floats2half2_rn(v1.z, v1.w));
    dst[i] = o;   // default store: keep in L2
}

// Accumulate dot of 8 fp16 pairs (16B vs 16B) into two fp32 chains.
__device__ __forceinline__ void acc16(const uint4& a, const uint4& b,
                                      float2& acc)
{
    const unsigned aw[4] = {a.x, a.y, a.z, a.w};
    const unsigned bw[4] = {b.x, b.y, b.z, b.w};
    #pragma unroll
    for (int i = 0; i < 4; i++) {
        __half2 ha = *reinterpret_cast<const __half2*>(&aw[i]);
        __half2 hb = *reinterpret_cast<const __half2*>(&bw[i]);
        float2 fa = __half22float2(ha);
        float2 fb = __half22float2(hb);
        acc.x = fmaf(fa.x, fb.x, acc.x);
        acc.y = fmaf(fa.y, fb.y, acc.y);
    }
}

// Proven scorer inner loop: 4 lanes per edge, 8 edges per warp, fp16 rows
// (256B = 16 x 16B chunks). Lane covers chunks {sub, sub+4, sub+8, sub+12}
// of both rows -> 8 independent LDG.128 per thread (MLP=8), ~32 regs.
__device__ __forceinline__ float dot_rows4(const uint4* __restrict__ srow,
                                           const uint4* __restrict__ drow,
                                           int sub)
{
    uint4 a0 = __ldg(&srow[sub]);
    uint4 b0 = __ldg(&drow[sub]);
    uint4 a1 = __ldg(&srow[sub + 4]);
    uint4 b1 = __ldg(&drow[sub + 4]);
    uint4 a2 = __ldg(&srow[sub + 8]);
    uint4 b2 = __ldg(&drow[sub + 8]);
    uint4 a3 = __ldg(&srow[sub + 12]);
    uint4 b3 = __ldg(&drow[sub + 12]);

    float2 acc0 = make_float2(0.f, 0.f);
    float2 acc1 = make_float2(0.f, 0.f);
    acc16(a0, b0, acc0);
    acc16(a1, b1, acc1);
    acc16(a2, b2, acc0);
    acc16(a3, b3, acc1);
    return (acc0.x + acc0.y) + (acc1.x + acc1.y);
}

// Single-etype scorer (srcTab/dstTab passed explicitly; clean access stream).
__global__ __launch_bounds__(256) void edge_dot1_h_kernel(
    const uint4* __restrict__ srcTab, const int* __restrict__ si,
    const uint4* __restrict__ dstTab, const int* __restrict__ di,
    float* __restrict__ out, int E)
{
    const int lane = threadIdx.x & 31;
    const int wib = threadIdx.x >> 5;
    const int sub = lane & 3;
    const int group = lane >> 2;

    const int e = blockIdx.x * 64 + wib * 8 + group;
    if (e >= E) return;

    const int s_idx = __ldcs(&si[e]);
    const int d_idx = __ldcs(&di[e]);

    float sum = dot_rows4(srcTab + (size_t)s_idx * 16,
                          dstTab + (size_t)d_idx * 16, sub);

    sum += __shfl_xor_sync(0xFFFFFFFFu, sum, 1);
    sum += __shfl_xor_sync(0xFFFFFFFFu, sum, 2);

    // Output is write-once: evict-first so it never displaces table lines.
    if (sub == 0) __stcs(&out[e], sum);
}

extern "C" void kernel_launch(void* const* d_in, const int* in_sizes, int n_in,
                              void* d_out, int out_size)
{
    const float* h_user = (const float*)d_in[0];
    const float* h_item = (const float*)d_in[1];
    const int* src_clicks    = (const int*)d_in[2];
    const int* dst_clicks    = (const int*)d_in[3];
    const int* src_clickedby = (const int*)d_in[4];
    const int* dst_clickedby = (const int*)d_in[5];
    const int* src_follows   = (const int*)d_in[6];
    const int* dst_follows   = (const int*)d_in[7];
    float* out = (float*)d_out;

    const int E = in_sizes[2];          // edges per etype (500000)

    static cudaStream_t s1 = nullptr;
    static cudaEvent_t ev_user = nullptr, ev_item = nullptr, ev_s1 = nullptr;
    if (!s1) {
        cudaStreamCreateWithFlags(&s1, cudaStreamNonBlocking);
        cudaEventCreateWithFlags(&ev_user, cudaEventDisableTiming);
        cudaEventCreateWithFlags(&ev_item, cudaEventDisableTiming);
        cudaEventCreateWithFlags(&ev_s1, cudaEventDisableTiming);
    }

    uint4* gu = nullptr; uint4* gi = nullptr;
    cudaGetSymbolAddress((void**)&gu, g_user_h);
    cudaGetSymbolAddress((void**)&gi, g_item_h);
    const int n8u = in_sizes[0] / 8;
    const int n8i = in_sizes[1] / 8;

    const int sblocks = (E + 63) / 64;  // 64 edges per block

    // origin: conv_user -> ev_user -> conv_item -> ev_item -> clicks -> wait s1
    // s1:     wait ev_user -> follows -> wait ev_item -> clickedby -> ev_s1
    convert_f32_to_f16_kernel<<<(n8u + 255) / 256, 256>>>(
        (const float4*)h_user, gu, n8u);
    cudaEventRecord(ev_user, 0);

    cudaStreamWaitEvent(s1, ev_user, 0);
    edge_dot1_h_kernel<<<sblocks, 256, 0, s1>>>(
        gu, src_follows, gu, dst_follows, out + 2 * (size_t)E, E);

    convert_f32_to_f16_kernel<<<(n8i + 255) / 256, 256>>>(
        (const float4*)h_item, gi, n8i);
    cudaEventRecord(ev_item, 0);

    cudaStreamWaitEvent(s1, ev_item, 0);
    edge_dot1_h_kernel<<<sblocks, 256, 0, s1>>>(
        gi, src_clickedby, gu, dst_clickedby, out + (size_t)E, E);
    cudaEventRecord(ev_s1, s1);

    edge_dot1_h_kernel<<<sblocks, 256>>>(
        gu, src_clicks, gi, dst_clicks, out, E);

    cudaStreamWaitEvent(0, ev_s1, 0);
}